// round 5
// baseline (speedup 1.0000x reference)
#include <cuda_runtime.h>
#include <cstddef>

#define DIMN 1024
#define NH   16
#define DK   64
#define BATCH 4
#define QL   1024
#define KL   1024

// Scratch (device globals: allocation-free rule)
__device__ float g_Qh[BATCH*NH*QL*DK];   // [b*16+h][q][d], pre-scaled by 1/8
__device__ float g_Kh[BATCH*NH*KL*DK];
__device__ float g_Vh[BATCH*NH*KL*DK];
__device__ float g_vals[BATCH*QL*DIMN];  // attention out, [b,q, d*16+h]
__device__ float g_W2[DIMN*DIMN];        // Wout @ Wout
__device__ unsigned char g_mask8[BATCH*QL*KL];
__device__ int g_isByte;
__device__ int g_allTrue;

// ---------------------------------------------------------------------------
__device__ __forceinline__ unsigned f2tf(float x) {
    unsigned r;
    asm("cvt.rna.tf32.f32 %0, %1;" : "=r"(r) : "f"(x));
    return r;
}

__device__ __forceinline__ void mma_tf32(float c[4], const unsigned a[4], const unsigned b[2]) {
    asm("mma.sync.aligned.m16n8k8.row.col.f32.tf32.tf32.f32 "
        "{%0,%1,%2,%3}, {%4,%5,%6,%7}, {%8,%9}, {%0,%1,%2,%3};"
        : "+f"(c[0]), "+f"(c[1]), "+f"(c[2]), "+f"(c[3])
        : "r"(a[0]), "r"(a[1]), "r"(a[2]), "r"(a[3]), "r"(b[0]), "r"(b[1]));
}

// ---------------------------------------------------------------------------
// Mask dtype detect (int32 vs byte)
// ---------------------------------------------------------------------------
__global__ void mask_detect_kernel(const unsigned char* __restrict__ m)
{
    __shared__ int found;
    if (threadIdx.x == 0) { found = 0; g_allTrue = 1; }
    __syncthreads();
    for (int i = threadIdx.x; i < 16384; i += blockDim.x)
        if ((i & 3) && m[i]) found = 1;
    __syncthreads();
    if (threadIdx.x == 0) g_isByte = found;
}

__global__ void mask_convert_kernel(const unsigned char* __restrict__ m, int n)
{
    int i = blockIdx.x * blockDim.x + threadIdx.x;
    int v = 1;
    if (i < n) {
        v = g_isByte ? (m[i] ? 1 : 0) : (((const unsigned*)m)[i] ? 1 : 0);
        g_mask8[i] = (unsigned char)v;
    }
    int all = __syncthreads_and(v);
    if (!all && threadIdx.x == 0) g_allTrue = 0;
}

// ---------------------------------------------------------------------------
// GEMM building blocks. Tiles: BM=BN=128, BK=32, 256 threads = 8 warps (4Mx2N).
// SMEM is stored in fragment-major layout:
//   A atom (am 0..7, ak 0..3): addr = (am*4+ak)*128 + lane*4 + fi   (LDS.128)
//   B atom (an 0..15, ak 0..3): addr = (an*4+ak)*64  + lane*2 + fi  (LDS.64)
// Double-buffered (2 x 8192 words = 64KB dynamic smem), register prefetch.
// ---------------------------------------------------------------------------
#define BUF_WORDS 8192

__device__ __forceinline__ void loadA_g(float4 pa[4], const float* A, int m0, int kk, int K, int tid) {
#pragma unroll
    for (int i = 0; i < 4; i++) {
        int f = tid + i * 256;
        int row = f >> 3, kq = (f & 7) * 4;
        pa[i] = *(const float4*)&A[(size_t)(m0 + row) * K + kk + kq];
    }
}
__device__ __forceinline__ void storeA_s(unsigned* As, const float4 pa[4], int tid) {
#pragma unroll
    for (int i = 0; i < 4; i++) {
        int f = tid + i * 256;
        int row = f >> 3, kq = (f & 7) * 4;
        int am = row >> 4, r = row & 15, ak = kq >> 3;
        int fi = ((r >> 3) & 1) | (((kq & 7) >= 4) ? 2 : 0);
        unsigned* base = &As[(am * 4 + ak) * 128 + (r & 7) * 16 + fi];
        base[0]  = f2tf(pa[i].x);
        base[4]  = f2tf(pa[i].y);
        base[8]  = f2tf(pa[i].z);
        base[12] = f2tf(pa[i].w);
    }
}
__device__ __forceinline__ void loadB_g(float4 pb[4], const float* W, int n0, int kk, int K, int tid) {
#pragma unroll
    for (int i = 0; i < 4; i++) {
        int f = tid + i * 256;
        int row = f >> 3, kq = (f & 7) * 4;
        pb[i] = *(const float4*)&W[(size_t)(n0 + row) * K + kk + kq];
    }
}
__device__ __forceinline__ void storeB_s(unsigned* Bs, const float4 pb[4], int tid) {
#pragma unroll
    for (int i = 0; i < 4; i++) {
        int f = tid + i * 256;
        int row = f >> 3, kq = (f & 7) * 4;
        int an = row >> 3, g = row & 7, ak = kq >> 3;
        int fi = ((kq & 7) >= 4) ? 1 : 0;
        unsigned* base = &Bs[(an * 4 + ak) * 64 + g * 8 + fi];
        base[0] = f2tf(pb[i].x);
        base[2] = f2tf(pb[i].y);
        base[4] = f2tf(pb[i].z);
        base[6] = f2tf(pb[i].w);
    }
}
// transposed B read (W stored [K][N] row-major, we need W^T): for W2 = Wout@Wout
__device__ __forceinline__ void loadBT_g(float4 pb[4], const float* W, int n0, int kk, int ldn, int tid) {
#pragma unroll
    for (int i = 0; i < 4; i++) {
        int f = tid + i * 256;
        int kr = f >> 5, nq = (f & 31) * 4;
        pb[i] = *(const float4*)&W[(size_t)(kk + kr) * ldn + n0 + nq];
    }
}
__device__ __forceinline__ void storeBT_s(unsigned* Bs, const float4 pb[4], int tid) {
#pragma unroll
    for (int i = 0; i < 4; i++) {
        int f = tid + i * 256;
        int kr = f >> 5, nq = (f & 31) * 4;
        int ak = kr >> 3, cc = kr & 7;
        int fi = (cc >= 4) ? 1 : 0;
        float v[4] = { pb[i].x, pb[i].y, pb[i].z, pb[i].w };
#pragma unroll
        for (int j = 0; j < 4; j++) {
            int n = nq + j;
            int an = n >> 3, g = n & 7;
            Bs[(an * 4 + ak) * 64 + (g * 4 + (cc & 3)) * 2 + fi] = f2tf(v[j]);
        }
    }
}

__device__ __forceinline__ void compute_tile(const unsigned* As, const unsigned* Bs,
                                             float c[2][8][4], int wm, int wn, int lane) {
#pragma unroll
    for (int ks = 0; ks < 4; ks++) {
        uint4 a0 = *(const uint4*)&As[((wm * 2 + 0) * 4 + ks) * 128 + lane * 4];
        uint4 a1 = *(const uint4*)&As[((wm * 2 + 1) * 4 + ks) * 128 + lane * 4];
        unsigned af0[4] = { a0.x, a0.y, a0.z, a0.w };
        unsigned af1[4] = { a1.x, a1.y, a1.z, a1.w };
#pragma unroll
        for (int nt = 0; nt < 8; nt++) {
            uint2 bv = *(const uint2*)&Bs[((wn * 8 + nt) * 4 + ks) * 64 + lane * 2];
            unsigned bf[2] = { bv.x, bv.y };
            mma_tf32(c[0][nt], af0, bf);
            mma_tf32(c[1][nt], af1, bf);
        }
    }
}

// ---------------------------------------------------------------------------
// MODE 0: C = A @ W^T (plain store)
// MODE 3: C = A @ W   (transposed-B staging; used for W2 = Wout @ Wout)
// ---------------------------------------------------------------------------
template<int MODE>
__global__ __launch_bounds__(256, 1)
void mma_gemm(const float* __restrict__ A, const float* __restrict__ W,
              float* __restrict__ C, int M, int N, int K)
{
    extern __shared__ unsigned sh[];
    const int tid = threadIdx.x;
    const int m0 = blockIdx.y * 128, n0 = blockIdx.x * 128;
    const int warp = tid >> 5, lane = tid & 31;
    const int wm = warp & 3, wn = warp >> 2;
    const int g = lane >> 2, t = lane & 3;

    float c[2][8][4];
#pragma unroll
    for (int mt = 0; mt < 2; mt++)
#pragma unroll
        for (int nt = 0; nt < 8; nt++)
#pragma unroll
            for (int i = 0; i < 4; i++) c[mt][nt][i] = 0.f;

    float4 pa[4], pb[4];
    loadA_g(pa, A, m0, 0, K, tid);
    if (MODE == 3) loadBT_g(pb, W, n0, 0, N, tid);
    else           loadB_g(pb, W, n0, 0, K, tid);
    storeA_s(sh, pa, tid);
    if (MODE == 3) storeBT_s(sh + 4096, pb, tid);
    else           storeB_s(sh + 4096, pb, tid);
    __syncthreads();

    int cur = 0;
    for (int kk = 32; kk < K; kk += 32) {
        loadA_g(pa, A, m0, kk, K, tid);
        if (MODE == 3) loadBT_g(pb, W, n0, kk, N, tid);
        else           loadB_g(pb, W, n0, kk, K, tid);
        compute_tile(sh + cur * BUF_WORDS, sh + cur * BUF_WORDS + 4096, c, wm, wn, lane);
        int nxt = cur ^ 1;
        storeA_s(sh + nxt * BUF_WORDS, pa, tid);
        if (MODE == 3) storeBT_s(sh + nxt * BUF_WORDS + 4096, pb, tid);
        else           storeB_s(sh + nxt * BUF_WORDS + 4096, pb, tid);
        __syncthreads();
        cur = nxt;
    }
    compute_tile(sh + cur * BUF_WORDS, sh + cur * BUF_WORDS + 4096, c, wm, wn, lane);

    // epilogue: plain store
#pragma unroll
    for (int mt = 0; mt < 2; mt++) {
        int r0 = m0 + wm * 32 + mt * 16 + g;
        int r1 = r0 + 8;
#pragma unroll
        for (int nt = 0; nt < 8; nt++) {
            int col = n0 + wn * 64 + nt * 8 + 2 * t;
            *(float2*)&C[(size_t)r0 * N + col] = make_float2(c[mt][nt][0], c[mt][nt][1]);
            *(float2*)&C[(size_t)r1 * N + col] = make_float2(c[mt][nt][2], c[mt][nt][3]);
        }
    }
}

// ---------------------------------------------------------------------------
// Merged projection kernel: grid.x 0..7 -> Q proj (dec@Wq^T, scaled scatter),
// grid.x 8..23 -> KV proj (enc@Wkv^T, K/V scatter). grid.y = M/128.
// ---------------------------------------------------------------------------
__global__ __launch_bounds__(256, 1)
void proj_gemm(const float* __restrict__ dec, const float* __restrict__ enc,
               const float* __restrict__ Wq, const float* __restrict__ Wkv)
{
    extern __shared__ unsigned sh[];
    const int tid = threadIdx.x;
    const bool isQ = blockIdx.x < 8;
    const float* A = isQ ? dec : enc;
    const float* W = isQ ? Wq : Wkv;
    const int n0 = (isQ ? blockIdx.x : (blockIdx.x - 8)) * 128;
    const int m0 = blockIdx.y * 128;
    const int K = DIMN;
    const int warp = tid >> 5, lane = tid & 31;
    const int wm = warp & 3, wn = warp >> 2;
    const int g = lane >> 2, t = lane & 3;

    float c[2][8][4];
#pragma unroll
    for (int mt = 0; mt < 2; mt++)
#pragma unroll
        for (int nt = 0; nt < 8; nt++)
#pragma unroll
            for (int i = 0; i < 4; i++) c[mt][nt][i] = 0.f;

    float4 pa[4], pb[4];
    loadA_g(pa, A, m0, 0, K, tid);
    loadB_g(pb, W, n0, 0, K, tid);
    storeA_s(sh, pa, tid);
    storeB_s(sh + 4096, pb, tid);
    __syncthreads();

    int cur = 0;
    for (int kk = 32; kk < K; kk += 32) {
        loadA_g(pa, A, m0, kk, K, tid);
        loadB_g(pb, W, n0, kk, K, tid);
        compute_tile(sh + cur * BUF_WORDS, sh + cur * BUF_WORDS + 4096, c, wm, wn, lane);
        int nxt = cur ^ 1;
        storeA_s(sh + nxt * BUF_WORDS, pa, tid);
        storeB_s(sh + nxt * BUF_WORDS + 4096, pb, tid);
        __syncthreads();
        cur = nxt;
    }
    compute_tile(sh + cur * BUF_WORDS, sh + cur * BUF_WORDS + 4096, c, wm, wn, lane);

    // scatter epilogue
#pragma unroll
    for (int mt = 0; mt < 2; mt++) {
        int r0 = wm * 32 + mt * 16 + g;
        int r1 = r0 + 8;
#pragma unroll
        for (int nt = 0; nt < 8; nt++) {
            int col = n0 + wn * 64 + nt * 8 + 2 * t;
#pragma unroll
            for (int e = 0; e < 4; e++) {
                int m = m0 + ((e < 2) ? r0 : r1);
                int n = col + (e & 1);
                float v = c[mt][nt][e];
                int b = m >> 10, q = m & 1023;
                if (isQ) {
                    int h = n & 15, d = n >> 4;
                    g_Qh[(((size_t)(b * NH + h) * QL + q) * DK) + d] = v * 0.125f;
                } else if (n < DIMN) {
                    int h = n & 15, d = n >> 4;
                    g_Kh[(((size_t)(b * NH + h) * KL + q) * DK) + d] = v;
                } else {
                    int nn = n - DIMN;
                    int h = nn & 15, d = nn >> 4;
                    g_Vh[(((size_t)(b * NH + h) * KL + q) * DK) + d] = v;
                }
            }
        }
    }
}

// ---------------------------------------------------------------------------
// Fused attention (unchanged — bit-identical numerics to R3 passing run)
// ---------------------------------------------------------------------------
#define ATT_LD 68
#define SMEM_ATTN (4 * 64 * ATT_LD * 4 + 64 * 64)

__global__ __launch_bounds__(128)
void attn_kernel(float* __restrict__ vals)
{
    extern __shared__ unsigned smU[];
    unsigned* Qs = smU;
    unsigned* Ks = Qs + 64 * ATT_LD;
    unsigned* Vt = Ks + 64 * ATT_LD;
    unsigned* Ps = Vt + 64 * ATT_LD;
    unsigned char* Ms = (unsigned char*)(Ps + 64 * ATT_LD);

    const int head = blockIdx.y;
    const int b = head >> 4, h = head & 15;
    const int q0 = blockIdx.x * 64;
    const int tid = threadIdx.x;
    const int w = tid >> 5, lane = tid & 31;
    const int g = lane >> 2, t = lane & 3;
    const int wq0 = w * 16;
    const int allTrue = g_allTrue;

    const float* Qp = g_Qh + (size_t)head * QL * DK;
    const float* Kp = g_Kh + (size_t)head * KL * DK;
    const float* Vp = g_Vh + (size_t)head * KL * DK;

#pragma unroll
    for (int i = 0; i < 8; i++) {
        int f = tid + i * 128;
        int row = f >> 4, dq = (f & 15) * 4;
        float4 qv = *(const float4*)&Qp[(size_t)(q0 + row) * DK + dq];
        unsigned* d = &Qs[row * ATT_LD + dq];
        d[0] = f2tf(qv.x); d[1] = f2tf(qv.y); d[2] = f2tf(qv.z); d[3] = f2tf(qv.w);
    }

    float o[8][4];
#pragma unroll
    for (int nt = 0; nt < 8; nt++)
#pragma unroll
        for (int i = 0; i < 4; i++) o[nt][i] = 0.f;
    float l0 = 0.f, l1 = 0.f;

    for (int k0 = 0; k0 < KL; k0 += 64) {
#pragma unroll
        for (int i = 0; i < 8; i++) {
            int f = tid + i * 128;
            int row = f >> 4, dq = (f & 15) * 4;
            float4 kv = *(const float4*)&Kp[(size_t)(k0 + row) * DK + dq];
            unsigned* d = &Ks[row * ATT_LD + dq];
            d[0] = f2tf(kv.x); d[1] = f2tf(kv.y); d[2] = f2tf(kv.z); d[3] = f2tf(kv.w);
            float4 vv = *(const float4*)&Vp[(size_t)(k0 + row) * DK + dq];
            Vt[(dq + 0) * ATT_LD + row] = f2tf(vv.x);
            Vt[(dq + 1) * ATT_LD + row] = f2tf(vv.y);
            Vt[(dq + 2) * ATT_LD + row] = f2tf(vv.z);
            Vt[(dq + 3) * ATT_LD + row] = f2tf(vv.w);
        }
        if (!allTrue) {
            const unsigned* mrow = (const unsigned*)(g_mask8 + ((size_t)(b * QL + q0)) * KL + k0);
#pragma unroll
            for (int i = 0; i < 8; i++) {
                int f = tid + i * 128;
                int qr = f >> 4, kq = f & 15;
                ((unsigned*)Ms)[qr * 16 + kq] =
                    *(const unsigned*)((const unsigned char*)mrow + (size_t)qr * KL + kq * 4);
            }
        }
        __syncthreads();

        float s[8][4];
#pragma unroll
        for (int nt = 0; nt < 8; nt++)
#pragma unroll
            for (int i = 0; i < 4; i++) s[nt][i] = 0.f;

#pragma unroll
        for (int ks = 0; ks < 8; ks++) {
            const int k8 = ks * 8;
            unsigned a[4];
            a[0] = Qs[(wq0 + g) * ATT_LD + k8 + t];
            a[1] = Qs[(wq0 + 8 + g) * ATT_LD + k8 + t];
            a[2] = Qs[(wq0 + g) * ATT_LD + k8 + 4 + t];
            a[3] = Qs[(wq0 + 8 + g) * ATT_LD + k8 + 4 + t];
#pragma unroll
            for (int nt = 0; nt < 8; nt++) {
                unsigned bf[2];
                bf[0] = Ks[(nt * 8 + g) * ATT_LD + k8 + t];
                bf[1] = Ks[(nt * 8 + g) * ATT_LD + k8 + 4 + t];
                mma_tf32(s[nt], a, bf);
            }
        }

        int qr0 = wq0 + g, qr1 = wq0 + 8 + g;
        float rs0 = 0.f, rs1 = 0.f;
#pragma unroll
        for (int nt = 0; nt < 8; nt++) {
            int kc = nt * 8 + 2 * t;
            float p00, p01, p10, p11;
            if (allTrue) {
                p00 = __expf(s[nt][0]); p01 = __expf(s[nt][1]);
                p10 = __expf(s[nt][2]); p11 = __expf(s[nt][3]);
            } else {
                p00 = Ms[qr0 * 64 + kc]     ? __expf(s[nt][0]) : 0.f;
                p01 = Ms[qr0 * 64 + kc + 1] ? __expf(s[nt][1]) : 0.f;
                p10 = Ms[qr1 * 64 + kc]     ? __expf(s[nt][2]) : 0.f;
                p11 = Ms[qr1 * 64 + kc + 1] ? __expf(s[nt][3]) : 0.f;
            }
            rs0 += p00 + p01;
            rs1 += p10 + p11;
            *(uint2*)&Ps[qr0 * ATT_LD + kc] = make_uint2(f2tf(p00), f2tf(p01));
            *(uint2*)&Ps[qr1 * ATT_LD + kc] = make_uint2(f2tf(p10), f2tf(p11));
        }
        rs0 += __shfl_xor_sync(0xffffffffu, rs0, 1);
        rs0 += __shfl_xor_sync(0xffffffffu, rs0, 2);
        rs1 += __shfl_xor_sync(0xffffffffu, rs1, 1);
        rs1 += __shfl_xor_sync(0xffffffffu, rs1, 2);
        l0 += rs0;
        l1 += rs1;
        __syncwarp();

#pragma unroll
        for (int ks = 0; ks < 8; ks++) {
            const int k8 = ks * 8;
            unsigned a[4];
            a[0] = Ps[(wq0 + g) * ATT_LD + k8 + t];
            a[1] = Ps[(wq0 + 8 + g) * ATT_LD + k8 + t];
            a[2] = Ps[(wq0 + g) * ATT_LD + k8 + 4 + t];
            a[3] = Ps[(wq0 + 8 + g) * ATT_LD + k8 + 4 + t];
#pragma unroll
            for (int nt = 0; nt < 8; nt++) {
                unsigned bf[2];
                bf[0] = Vt[(nt * 8 + g) * ATT_LD + k8 + t];
                bf[1] = Vt[(nt * 8 + g) * ATT_LD + k8 + 4 + t];
                mma_tf32(o[nt], a, bf);
            }
        }
        __syncthreads();
    }

    float inv0 = 1.f / l0, inv1 = 1.f / l1;
    int qa = q0 + wq0 + g, qb = qa + 8;
#pragma unroll
    for (int nt = 0; nt < 8; nt++) {
        int d = nt * 8 + 2 * t;
        float* base0 = &g_vals[((size_t)(b * QL + qa)) * DIMN + d * NH + h];
        float* base1 = &g_vals[((size_t)(b * QL + qb)) * DIMN + d * NH + h];
        base0[0]  = o[nt][0] * inv0;
        base0[NH] = o[nt][1] * inv0;
        base1[0]  = o[nt][2] * inv1;
        base1[NH] = o[nt][3] * inv1;
    }
    (void)vals;
}

// ---------------------------------------------------------------------------
extern "C" void kernel_launch(void* const* d_in, const int* in_sizes, int n_in,
                              void* d_out, int out_size)
{
    const float* dec  = (const float*)d_in[0];
    const float* enc  = (const float*)d_in[1];
    const unsigned char* mask = (const unsigned char*)d_in[2];
    const float* Wq   = (const float*)d_in[3];
    const float* Wkv  = (const float*)d_in[4];
    const float* Wout = (const float*)d_in[5];
    float* out = (float*)d_out;

    float *vals_p, *w2_p;
    cudaGetSymbolAddress((void**)&vals_p, g_vals);
    cudaGetSymbolAddress((void**)&w2_p, g_W2);

    const int GEMM_SMEM = 2 * BUF_WORDS * 4;  // 64KB
    cudaFuncSetAttribute(mma_gemm<0>, cudaFuncAttributeMaxDynamicSharedMemorySize, GEMM_SMEM);
    cudaFuncSetAttribute(mma_gemm<3>, cudaFuncAttributeMaxDynamicSharedMemorySize, GEMM_SMEM);
    cudaFuncSetAttribute(proj_gemm,   cudaFuncAttributeMaxDynamicSharedMemorySize, GEMM_SMEM);
    cudaFuncSetAttribute(attn_kernel, cudaFuncAttributeMaxDynamicSharedMemorySize, SMEM_ATTN);

    const int M = BATCH * QL; // 4096
    const int NMASK = BATCH * QL * KL;
    dim3 blk(256);

    mask_detect_kernel<<<1, 256>>>(mask);
    mask_convert_kernel<<<(NMASK + 255) / 256, 256>>>(mask, NMASK);

    // W2 = Wout @ Wout  (A @ B with transposed-B staging)
    mma_gemm<3><<<dim3(8, 8), blk, GEMM_SMEM>>>(Wout, Wout, w2_p, DIMN, DIMN, DIMN);
    // merged Q + KV projections (scattered per-head)
    proj_gemm<<<dim3(24, M / 128), blk, GEMM_SMEM>>>(dec, enc, Wq, Wkv);
    // fused attention -> g_vals
    attn_kernel<<<dim3(QL / 64, BATCH * NH), dim3(128), SMEM_ATTN>>>(vals_p);
    // out = vals @ W2^T
    mma_gemm<0><<<dim3(8, M / 128), blk, GEMM_SMEM>>>(vals_p, w2_p, out, M, DIMN, DIMN);
}

// round 6
// speedup vs baseline: 1.2655x; 1.2655x over previous
#include <cuda_runtime.h>
#include <cstddef>

#define DIMN 1024
#define NH   16
#define DK   64
#define BATCH 4
#define QL   1024
#define KL   1024

// Scratch (device globals: allocation-free rule)
__device__ float g_Qh[BATCH*NH*QL*DK];   // [b*16+h][q][d], pre-scaled by 1/8
__device__ float g_Kh[BATCH*NH*KL*DK];
__device__ float g_Vh[BATCH*NH*KL*DK];
__device__ float g_vals[BATCH*QL*DIMN];  // attention out, [b,q, d*16+h]
__device__ float g_W2[DIMN*DIMN];        // Wout @ Wout
__device__ unsigned char g_mask8[BATCH*QL*KL];
__device__ int g_isByte;
__device__ int g_allTrue;

// ---------------------------------------------------------------------------
__device__ __forceinline__ unsigned f2tf(float x) {
    unsigned r;
    asm("cvt.rna.tf32.f32 %0, %1;" : "=r"(r) : "f"(x));
    return r;
}

__device__ __forceinline__ void mma_tf32(float c[4], const unsigned a[4], const unsigned b[2]) {
    asm("mma.sync.aligned.m16n8k8.row.col.f32.tf32.tf32.f32 "
        "{%0,%1,%2,%3}, {%4,%5,%6,%7}, {%8,%9}, {%0,%1,%2,%3};"
        : "+f"(c[0]), "+f"(c[1]), "+f"(c[2]), "+f"(c[3])
        : "r"(a[0]), "r"(a[1]), "r"(a[2]), "r"(a[3]), "r"(b[0]), "r"(b[1]));
}

// ---------------------------------------------------------------------------
// Mask dtype detect (int32 vs byte)
// ---------------------------------------------------------------------------
__global__ void mask_detect_kernel(const unsigned char* __restrict__ m)
{
    __shared__ int found;
    if (threadIdx.x == 0) { found = 0; g_allTrue = 1; }
    __syncthreads();
    for (int i = threadIdx.x; i < 16384; i += blockDim.x)
        if ((i & 3) && m[i]) found = 1;
    __syncthreads();
    if (threadIdx.x == 0) g_isByte = found;
}

__global__ void mask_convert_kernel(const unsigned char* __restrict__ m, int n)
{
    int i = blockIdx.x * blockDim.x + threadIdx.x;
    int v = 1;
    if (i < n) {
        v = g_isByte ? (m[i] ? 1 : 0) : (((const unsigned*)m)[i] ? 1 : 0);
        g_mask8[i] = (unsigned char)v;
    }
    int all = __syncthreads_and(v);
    if (!all && threadIdx.x == 0) g_allTrue = 0;
}

// ---------------------------------------------------------------------------
// GEMM core: BM=BN=128, BK=32, 128 threads = 4 warps (2M x 2N), warp 64x64.
// SMEM row-major stride 36 (conflict-free frag loads: bank = 4g+t).
// Staging stores are 16B-aligned consecutive -> STS.128, conflict-free.
// Fragment traffic: 4KB per warp-k8 for 32 MMAs (0.0625 B/FLOP).
// ---------------------------------------------------------------------------
#define LDS_T 36

__device__ __forceinline__ void stageA(unsigned* As, const float* A, int m0, int kk, int K, int tid) {
#pragma unroll
    for (int i = 0; i < 8; i++) {
        int f = tid + i * 128;
        int row = f >> 3, kq = (f & 7) * 4;
        float4 v = *(const float4*)&A[(size_t)(m0 + row) * K + kk + kq];
        unsigned* d = &As[row * LDS_T + kq];
        d[0] = f2tf(v.x); d[1] = f2tf(v.y); d[2] = f2tf(v.z); d[3] = f2tf(v.w);
    }
}
// transposed-B staging (W row-major [K][N], want Bs[n][k]) — used only by W2
__device__ __forceinline__ void stageBT(unsigned* Bs, const float* W, int n0, int kk, int ldn, int tid) {
#pragma unroll
    for (int i = 0; i < 8; i++) {
        int f = tid + i * 128;
        int kr = f >> 5, nq = (f & 31) * 4;
        float4 v = *(const float4*)&W[(size_t)(kk + kr) * ldn + n0 + nq];
        Bs[(nq + 0) * LDS_T + kr] = f2tf(v.x);
        Bs[(nq + 1) * LDS_T + kr] = f2tf(v.y);
        Bs[(nq + 2) * LDS_T + kr] = f2tf(v.z);
        Bs[(nq + 3) * LDS_T + kr] = f2tf(v.w);
    }
}

__device__ __forceinline__ void compute_tile(const unsigned* As, const unsigned* Bs,
                                             float c[4][8][4], int wm, int wn, int g, int t) {
#pragma unroll
    for (int ks = 0; ks < 4; ks++) {
        const int k8 = ks * 8;
        unsigned a[4][4];
#pragma unroll
        for (int mt = 0; mt < 4; mt++) {
            int r = wm * 64 + mt * 16;
            a[mt][0] = As[(r + g) * LDS_T + k8 + t];
            a[mt][1] = As[(r + 8 + g) * LDS_T + k8 + t];
            a[mt][2] = As[(r + g) * LDS_T + k8 + 4 + t];
            a[mt][3] = As[(r + 8 + g) * LDS_T + k8 + 4 + t];
        }
#pragma unroll
        for (int nt = 0; nt < 8; nt++) {
            int cx = wn * 64 + nt * 8;
            unsigned bf[2];
            bf[0] = Bs[(cx + g) * LDS_T + k8 + t];
            bf[1] = Bs[(cx + g) * LDS_T + k8 + 4 + t];
#pragma unroll
            for (int mt = 0; mt < 4; mt++)
                mma_tf32(c[mt][nt], a[mt], bf);
        }
    }
}

// ---------------------------------------------------------------------------
// MODE 0: C = A @ W^T (plain store)
// MODE 3: C = A @ W   (transposed-B staging; W2 = Wout @ Wout)
// ---------------------------------------------------------------------------
template<int MODE>
__global__ __launch_bounds__(128, 2)
void mma_gemm(const float* __restrict__ A, const float* __restrict__ W,
              float* __restrict__ C, int M, int N, int K)
{
    __shared__ unsigned As[128 * LDS_T];
    __shared__ unsigned Bs[128 * LDS_T];

    const int tid = threadIdx.x;
    const int m0 = blockIdx.y * 128, n0 = blockIdx.x * 128;
    const int warp = tid >> 5, lane = tid & 31;
    const int wm = warp & 1, wn = warp >> 1;
    const int g = lane >> 2, t = lane & 3;

    float c[4][8][4];
#pragma unroll
    for (int mt = 0; mt < 4; mt++)
#pragma unroll
        for (int nt = 0; nt < 8; nt++)
#pragma unroll
            for (int i = 0; i < 4; i++) c[mt][nt][i] = 0.f;

    for (int kk = 0; kk < K; kk += 32) {
        stageA(As, A, m0, kk, K, tid);
        if (MODE == 3) stageBT(Bs, W, n0, kk, N, tid);
        else           stageA(Bs, W, n0, kk, K, tid);   // B rows = W rows (W @ W^T form)
        __syncthreads();
        compute_tile(As, Bs, c, wm, wn, g, t);
        __syncthreads();
    }

#pragma unroll
    for (int mt = 0; mt < 4; mt++) {
        int r0 = m0 + wm * 64 + mt * 16 + g;
        int r1 = r0 + 8;
#pragma unroll
        for (int nt = 0; nt < 8; nt++) {
            int col = n0 + wn * 64 + nt * 8 + 2 * t;
            *(float2*)&C[(size_t)r0 * N + col] = make_float2(c[mt][nt][0], c[mt][nt][1]);
            *(float2*)&C[(size_t)r1 * N + col] = make_float2(c[mt][nt][2], c[mt][nt][3]);
        }
    }
}

// ---------------------------------------------------------------------------
// Merged projections: grid.x 0..7 -> Q proj (dec@Wq^T, scaled per-head scatter)
//                     grid.x 8..23 -> KV proj (enc@Wkv^T, K/V per-head scatter)
// ---------------------------------------------------------------------------
__global__ __launch_bounds__(128, 2)
void proj_gemm(const float* __restrict__ dec, const float* __restrict__ enc,
               const float* __restrict__ Wq, const float* __restrict__ Wkv)
{
    __shared__ unsigned As[128 * LDS_T];
    __shared__ unsigned Bs[128 * LDS_T];

    const int tid = threadIdx.x;
    const bool isQ = blockIdx.x < 8;
    const float* A = isQ ? dec : enc;
    const float* W = isQ ? Wq : Wkv;
    const int n0 = (isQ ? blockIdx.x : (blockIdx.x - 8)) * 128;
    const int m0 = blockIdx.y * 128;
    const int K = DIMN;
    const int warp = tid >> 5, lane = tid & 31;
    const int wm = warp & 1, wn = warp >> 1;
    const int g = lane >> 2, t = lane & 3;

    float c[4][8][4];
#pragma unroll
    for (int mt = 0; mt < 4; mt++)
#pragma unroll
        for (int nt = 0; nt < 8; nt++)
#pragma unroll
            for (int i = 0; i < 4; i++) c[mt][nt][i] = 0.f;

    for (int kk = 0; kk < K; kk += 32) {
        stageA(As, A, m0, kk, K, tid);
        stageA(Bs, W, n0, kk, K, tid);
        __syncthreads();
        compute_tile(As, Bs, c, wm, wn, g, t);
        __syncthreads();
    }

    // scatter epilogue (validated in R3/R5)
#pragma unroll
    for (int mt = 0; mt < 4; mt++) {
        int r0 = wm * 64 + mt * 16 + g;
        int r1 = r0 + 8;
#pragma unroll
        for (int nt = 0; nt < 8; nt++) {
            int col = n0 + wn * 64 + nt * 8 + 2 * t;
#pragma unroll
            for (int e = 0; e < 4; e++) {
                int m = m0 + ((e < 2) ? r0 : r1);
                int n = col + (e & 1);
                float v = c[mt][nt][e];
                int b = m >> 10, q = m & 1023;
                if (isQ) {
                    int h = n & 15, d = n >> 4;
                    g_Qh[(((size_t)(b * NH + h) * QL + q) * DK) + d] = v * 0.125f;
                } else if (n < DIMN) {
                    int h = n & 15, d = n >> 4;
                    g_Kh[(((size_t)(b * NH + h) * KL + q) * DK) + d] = v;
                } else {
                    int nn = n - DIMN;
                    int h = nn & 15, d = nn >> 4;
                    g_Vh[(((size_t)(b * NH + h) * KL + q) * DK) + d] = v;
                }
            }
        }
    }
}

// ---------------------------------------------------------------------------
// Fused attention (unchanged — bit-identical numerics to R3/R5 passing runs)
// ---------------------------------------------------------------------------
#define ATT_LD 68
#define SMEM_ATTN (4 * 64 * ATT_LD * 4 + 64 * 64)

__global__ __launch_bounds__(128)
void attn_kernel(float* __restrict__ vals)
{
    extern __shared__ unsigned smU[];
    unsigned* Qs = smU;
    unsigned* Ks = Qs + 64 * ATT_LD;
    unsigned* Vt = Ks + 64 * ATT_LD;
    unsigned* Ps = Vt + 64 * ATT_LD;
    unsigned char* Ms = (unsigned char*)(Ps + 64 * ATT_LD);

    const int head = blockIdx.y;
    const int b = head >> 4, h = head & 15;
    const int q0 = blockIdx.x * 64;
    const int tid = threadIdx.x;
    const int w = tid >> 5, lane = tid & 31;
    const int g = lane >> 2, t = lane & 3;
    const int wq0 = w * 16;
    const int allTrue = g_allTrue;

    const float* Qp = g_Qh + (size_t)head * QL * DK;
    const float* Kp = g_Kh + (size_t)head * KL * DK;
    const float* Vp = g_Vh + (size_t)head * KL * DK;

#pragma unroll
    for (int i = 0; i < 8; i++) {
        int f = tid + i * 128;
        int row = f >> 4, dq = (f & 15) * 4;
        float4 qv = *(const float4*)&Qp[(size_t)(q0 + row) * DK + dq];
        unsigned* d = &Qs[row * ATT_LD + dq];
        d[0] = f2tf(qv.x); d[1] = f2tf(qv.y); d[2] = f2tf(qv.z); d[3] = f2tf(qv.w);
    }

    float o[8][4];
#pragma unroll
    for (int nt = 0; nt < 8; nt++)
#pragma unroll
        for (int i = 0; i < 4; i++) o[nt][i] = 0.f;
    float l0 = 0.f, l1 = 0.f;

    for (int k0 = 0; k0 < KL; k0 += 64) {
#pragma unroll
        for (int i = 0; i < 8; i++) {
            int f = tid + i * 128;
            int row = f >> 4, dq = (f & 15) * 4;
            float4 kv = *(const float4*)&Kp[(size_t)(k0 + row) * DK + dq];
            unsigned* d = &Ks[row * ATT_LD + dq];
            d[0] = f2tf(kv.x); d[1] = f2tf(kv.y); d[2] = f2tf(kv.z); d[3] = f2tf(kv.w);
            float4 vv = *(const float4*)&Vp[(size_t)(k0 + row) * DK + dq];
            Vt[(dq + 0) * ATT_LD + row] = f2tf(vv.x);
            Vt[(dq + 1) * ATT_LD + row] = f2tf(vv.y);
            Vt[(dq + 2) * ATT_LD + row] = f2tf(vv.z);
            Vt[(dq + 3) * ATT_LD + row] = f2tf(vv.w);
        }
        if (!allTrue) {
            const unsigned* mrow = (const unsigned*)(g_mask8 + ((size_t)(b * QL + q0)) * KL + k0);
#pragma unroll
            for (int i = 0; i < 8; i++) {
                int f = tid + i * 128;
                int qr = f >> 4, kq = f & 15;
                ((unsigned*)Ms)[qr * 16 + kq] =
                    *(const unsigned*)((const unsigned char*)mrow + (size_t)qr * KL + kq * 4);
            }
        }
        __syncthreads();

        float s[8][4];
#pragma unroll
        for (int nt = 0; nt < 8; nt++)
#pragma unroll
            for (int i = 0; i < 4; i++) s[nt][i] = 0.f;

#pragma unroll
        for (int ks = 0; ks < 8; ks++) {
            const int k8 = ks * 8;
            unsigned a[4];
            a[0] = Qs[(wq0 + g) * ATT_LD + k8 + t];
            a[1] = Qs[(wq0 + 8 + g) * ATT_LD + k8 + t];
            a[2] = Qs[(wq0 + g) * ATT_LD + k8 + 4 + t];
            a[3] = Qs[(wq0 + 8 + g) * ATT_LD + k8 + 4 + t];
#pragma unroll
            for (int nt = 0; nt < 8; nt++) {
                unsigned bf[2];
                bf[0] = Ks[(nt * 8 + g) * ATT_LD + k8 + t];
                bf[1] = Ks[(nt * 8 + g) * ATT_LD + k8 + 4 + t];
                mma_tf32(s[nt], a, bf);
            }
        }

        int qr0 = wq0 + g, qr1 = wq0 + 8 + g;
        float rs0 = 0.f, rs1 = 0.f;
#pragma unroll
        for (int nt = 0; nt < 8; nt++) {
            int kc = nt * 8 + 2 * t;
            float p00, p01, p10, p11;
            if (allTrue) {
                p00 = __expf(s[nt][0]); p01 = __expf(s[nt][1]);
                p10 = __expf(s[nt][2]); p11 = __expf(s[nt][3]);
            } else {
                p00 = Ms[qr0 * 64 + kc]     ? __expf(s[nt][0]) : 0.f;
                p01 = Ms[qr0 * 64 + kc + 1] ? __expf(s[nt][1]) : 0.f;
                p10 = Ms[qr1 * 64 + kc]     ? __expf(s[nt][2]) : 0.f;
                p11 = Ms[qr1 * 64 + kc + 1] ? __expf(s[nt][3]) : 0.f;
            }
            rs0 += p00 + p01;
            rs1 += p10 + p11;
            *(uint2*)&Ps[qr0 * ATT_LD + kc] = make_uint2(f2tf(p00), f2tf(p01));
            *(uint2*)&Ps[qr1 * ATT_LD + kc] = make_uint2(f2tf(p10), f2tf(p11));
        }
        rs0 += __shfl_xor_sync(0xffffffffu, rs0, 1);
        rs0 += __shfl_xor_sync(0xffffffffu, rs0, 2);
        rs1 += __shfl_xor_sync(0xffffffffu, rs1, 1);
        rs1 += __shfl_xor_sync(0xffffffffu, rs1, 2);
        l0 += rs0;
        l1 += rs1;
        __syncwarp();

#pragma unroll
        for (int ks = 0; ks < 8; ks++) {
            const int k8 = ks * 8;
            unsigned a[4];
            a[0] = Ps[(wq0 + g) * ATT_LD + k8 + t];
            a[1] = Ps[(wq0 + 8 + g) * ATT_LD + k8 + t];
            a[2] = Ps[(wq0 + g) * ATT_LD + k8 + 4 + t];
            a[3] = Ps[(wq0 + 8 + g) * ATT_LD + k8 + 4 + t];
#pragma unroll
            for (int nt = 0; nt < 8; nt++) {
                unsigned bf[2];
                bf[0] = Vt[(nt * 8 + g) * ATT_LD + k8 + t];
                bf[1] = Vt[(nt * 8 + g) * ATT_LD + k8 + 4 + t];
                mma_tf32(o[nt], a, bf);
            }
        }
        __syncthreads();
    }

    float inv0 = 1.f / l0, inv1 = 1.f / l1;
    int qa = q0 + wq0 + g, qb = qa + 8;
#pragma unroll
    for (int nt = 0; nt < 8; nt++) {
        int d = nt * 8 + 2 * t;
        float* base0 = &g_vals[((size_t)(b * QL + qa)) * DIMN + d * NH + h];
        float* base1 = &g_vals[((size_t)(b * QL + qb)) * DIMN + d * NH + h];
        base0[0]  = o[nt][0] * inv0;
        base0[NH] = o[nt][1] * inv0;
        base1[0]  = o[nt][2] * inv1;
        base1[NH] = o[nt][3] * inv1;
    }
    (void)vals;
}

// ---------------------------------------------------------------------------
extern "C" void kernel_launch(void* const* d_in, const int* in_sizes, int n_in,
                              void* d_out, int out_size)
{
    const float* dec  = (const float*)d_in[0];
    const float* enc  = (const float*)d_in[1];
    const unsigned char* mask = (const unsigned char*)d_in[2];
    const float* Wq   = (const float*)d_in[3];
    const float* Wkv  = (const float*)d_in[4];
    const float* Wout = (const float*)d_in[5];
    float* out = (float*)d_out;

    float *vals_p, *w2_p;
    cudaGetSymbolAddress((void**)&vals_p, g_vals);
    cudaGetSymbolAddress((void**)&w2_p, g_W2);

    cudaFuncSetAttribute(attn_kernel, cudaFuncAttributeMaxDynamicSharedMemorySize, SMEM_ATTN);

    const int M = BATCH * QL; // 4096
    const int NMASK = BATCH * QL * KL;
    dim3 blk(128);

    mask_detect_kernel<<<1, 256>>>(mask);
    mask_convert_kernel<<<(NMASK + 255) / 256, 256>>>(mask, NMASK);

    // W2 = Wout @ Wout  (A @ B with transposed-B staging)
    mma_gemm<3><<<dim3(8, 8), blk>>>(Wout, Wout, w2_p, DIMN, DIMN, DIMN);
    // merged Q + KV projections (scattered per-head)
    proj_gemm<<<dim3(24, M / 128), blk>>>(dec, enc, Wq, Wkv);
    // fused attention -> g_vals
    attn_kernel<<<dim3(QL / 64, BATCH * NH), dim3(128), SMEM_ATTN>>>(vals_p);
    // out = vals @ W2^T
    mma_gemm<0><<<dim3(8, M / 128), blk>>>(vals_p, w2_p, out, M, DIMN, DIMN);
}